// round 5
// baseline (speedup 1.0000x reference)
#include <cuda_runtime.h>
#include <cuda_fp8.h>
#include <cstdint>
#include <cstddef>

// ---------------- problem dims ----------------
#define MDIM 16384
#define KDIM 4096
#define NDIM 4096

// ---------------- GEMM tiling ----------------
#define BM 128
#define BN 256
#define BK 128            // fp8 bytes per k-step
#define STAGES 4
#define KT (KDIM / BK)    // 32 k-iterations
#define STAGE_A_BYTES (BM * BK)                    // 16 KB
#define STAGE_B_BYTES (BN * BK)                    // 32 KB
#define STAGE_BYTES (STAGE_A_BYTES + STAGE_B_BYTES)  // 48 KB
#define GEMM_SMEM (STAGES * STAGE_BYTES)           // 192 KB

// ---------------- scratch (no allocations allowed) ----------------
__device__ __align__(1024) unsigned char g_xq[(size_t)MDIM * KDIM];   // 64 MB fp8 [M,K]
__device__ __align__(1024) unsigned char g_wqt[(size_t)NDIM * KDIM];  // 16 MB fp8 [N,K]
__device__ unsigned g_amax[2];
__device__ float g_scales[3];   // sx, sw, 1/(sx*sw)

// ---------------- helpers ----------------
__device__ __forceinline__ uint32_t smem_u32(const void* p) {
    uint32_t a;
    asm("{ .reg .u64 t; cvta.to.shared.u64 t, %1; cvt.u32.u64 %0, t; }" : "=r"(a) : "l"(p));
    return a;
}

__device__ __forceinline__ void cp_async16(uint32_t saddr, const void* gptr) {
    asm volatile("cp.async.cg.shared.global [%0], [%1], 16;" :: "r"(saddr), "l"(gptr) : "memory");
}

#define CP_COMMIT() asm volatile("cp.async.commit_group;" ::: "memory")
#define CP_WAIT2()  asm volatile("cp.async.wait_group 2;" ::: "memory")

__device__ __forceinline__ void ldsm_x4(uint32_t& r0, uint32_t& r1, uint32_t& r2, uint32_t& r3, uint32_t addr) {
    asm volatile("ldmatrix.sync.aligned.m8n8.x4.shared.b16 {%0,%1,%2,%3}, [%4];"
                 : "=r"(r0), "=r"(r1), "=r"(r2), "=r"(r3) : "r"(addr));
}

__device__ __forceinline__ void mma_fp8(float& c0, float& c1, float& c2, float& c3,
                                        uint32_t a0, uint32_t a1, uint32_t a2, uint32_t a3,
                                        uint32_t b0, uint32_t b1) {
    asm volatile(
        "mma.sync.aligned.m16n8k32.row.col.f32.e4m3.e4m3.f32 "
        "{%0,%1,%2,%3}, {%4,%5,%6,%7}, {%8,%9}, {%0,%1,%2,%3};"
        : "+f"(c0), "+f"(c1), "+f"(c2), "+f"(c3)
        : "r"(a0), "r"(a1), "r"(a2), "r"(a3), "r"(b0), "r"(b1));
}

// ---------------- pre-pass kernels ----------------
__global__ void zero_kernel() {
    if (threadIdx.x < 2) g_amax[threadIdx.x] = 0u;
}

__global__ void absmax_kernel(const float4* __restrict__ v, int n4, int slot) {
    float m = 0.f;
    for (int i = blockIdx.x * blockDim.x + threadIdx.x; i < n4; i += gridDim.x * blockDim.x) {
        float4 t = v[i];
        m = fmaxf(m, fmaxf(fmaxf(fabsf(t.x), fabsf(t.y)), fmaxf(fabsf(t.z), fabsf(t.w))));
    }
    #pragma unroll
    for (int o = 16; o; o >>= 1) m = fmaxf(m, __shfl_xor_sync(0xFFFFFFFFu, m, o));
    if ((threadIdx.x & 31) == 0) atomicMax(&g_amax[slot], __float_as_uint(m));
}

__global__ void scale_kernel() {
    float sx = 448.0f / __uint_as_float(g_amax[0]);
    float sw = 448.0f / __uint_as_float(g_amax[1]);
    g_scales[0] = sx;
    g_scales[1] = sw;
    g_scales[2] = 1.0f / (sx * sw);
}

// quantize x [M,K] fp32 -> fp8 e4m3 (same layout)
__global__ void quant_x_kernel(const float4* __restrict__ x) {
    float s = g_scales[0];
    unsigned i = blockIdx.x * blockDim.x + threadIdx.x;
    float4 v = x[i];
    unsigned lo = __nv_cvt_float2_to_fp8x2(make_float2(v.x * s, v.y * s), __NV_SATFINITE, __NV_E4M3);
    unsigned hi = __nv_cvt_float2_to_fp8x2(make_float2(v.z * s, v.w * s), __NV_SATFINITE, __NV_E4M3);
    reinterpret_cast<unsigned*>(g_xq)[i] = (lo & 0xFFFFu) | (hi << 16);
}

// quantize + transpose w [K,N] fp32 -> wq_t [N,K] fp8
__global__ void quant_wt_kernel(const float* __restrict__ w) {
    __shared__ unsigned char tile[32][33];
    float s = g_scales[1];
    int n0 = blockIdx.x * 32, k0 = blockIdx.y * 32;
    int tx = threadIdx.x, ty = threadIdx.y;   // 32 x 8
    #pragma unroll
    for (int j = 0; j < 4; j++) {
        int k = k0 + ty + j * 8;
        float v = w[(size_t)k * NDIM + n0 + tx] * s;
        tile[ty + j * 8][tx] = __nv_cvt_float_to_fp8(v, __NV_SATFINITE, __NV_E4M3);
    }
    __syncthreads();
    #pragma unroll
    for (int j = 0; j < 4; j++) {
        int r = ty + j * 8;
        g_wqt[(size_t)(n0 + r) * KDIM + k0 + tx] = tile[tx][r];
    }
}

// ---------------- fp8 GEMM via mma.sync m16n8k32 ----------------
// CTA: 128x256, 8 warps (2x4), warp tile 64x64. 4-stage cp.async pipeline,
// fragment double-buffering across ks so LDSM latency hides under MMAs.
__global__ void __launch_bounds__(256, 1) gemm_kernel(float* __restrict__ out) {
    extern __shared__ __align__(1024) unsigned char smem[];
    const uint32_t sb = smem_u32(smem);

    const int tid = threadIdx.x;
    const int w = tid >> 5, lane = tid & 31;
    const int wm = w & 1;            // m offset 0/64
    const int wn = w >> 1;           // n offset 0/64/128/192

    // ---- CTA raster swizzle: groups of 16(m) x 16(n) CTAs ----
    int lin = blockIdx.y * gridDim.x + blockIdx.x;   // grid = (16, 128)
    int grp = lin >> 8;
    int rem = lin & 255;
    const int m0 = (grp * 16 + (rem & 15)) * BM;
    const int n0 = (rem >> 4) * BN;

    const unsigned char* gA = g_xq  + (size_t)m0 * KDIM;
    const unsigned char* gB = g_wqt + (size_t)n0 * KDIM;

    // ---- cp.async mapping ----
    const int ld_row0 = tid >> 3;
    const int ld_c16  = tid & 7;
    const uint32_t ld_soff = (uint32_t)ld_row0 * BK + (uint32_t)((ld_c16 ^ (ld_row0 & 7)) << 4);
    const size_t   ld_goff = (size_t)ld_row0 * KDIM + (size_t)(ld_c16 << 4);

    // ---- ldmatrix per-lane addressing ----
    int a_row[4];
    #pragma unroll
    for (int mi = 0; mi < 4; mi++) a_row[mi] = wm * 64 + mi * 16 + (lane & 15);
    const int a_kh = lane >> 4;
    int b_row[4];
    #pragma unroll
    for (int g = 0; g < 4; g++) b_row[g] = wn * 64 + g * 16 + (lane & 7) + ((lane >> 4) << 3);
    const int b_kp = (lane >> 3) & 1;

    float acc[4][8][4];
    #pragma unroll
    for (int mi = 0; mi < 4; mi++)
        #pragma unroll
        for (int ni = 0; ni < 8; ni++)
            #pragma unroll
            for (int q = 0; q < 4; q++) acc[mi][ni][q] = 0.f;

    // ---- prologue: load stages 0..2 ----
    #pragma unroll
    for (int s = 0; s < STAGES - 1; s++) {
        uint32_t sA = sb + s * STAGE_BYTES;
        uint32_t sB = sA + STAGE_A_BYTES;
        size_t k0 = (size_t)s * BK;
        #pragma unroll
        for (int t = 0; t < 4; t++)
            cp_async16(sA + ld_soff + t * 32 * BK, gA + ld_goff + (size_t)(t * 32) * KDIM + k0);
        #pragma unroll
        for (int t = 0; t < 8; t++)
            cp_async16(sB + ld_soff + t * 32 * BK, gB + ld_goff + (size_t)(t * 32) * KDIM + k0);
        CP_COMMIT();
    }

    uint32_t aF[2][16], bF[2][16];

    // fragment loader: stage base addresses + ks -> buffer
    auto load_frags = [&](int buf, uint32_t sA, uint32_t sB, int ks) {
        #pragma unroll
        for (int mi = 0; mi < 4; mi++) {
            int r = a_row[mi];
            int c16 = (2 * ks + a_kh) ^ (r & 7);
            ldsm_x4(aF[buf][mi * 4 + 0], aF[buf][mi * 4 + 1], aF[buf][mi * 4 + 2], aF[buf][mi * 4 + 3],
                    sA + (uint32_t)r * BK + (uint32_t)(c16 << 4));
        }
        #pragma unroll
        for (int g = 0; g < 4; g++) {
            int r = b_row[g];
            int c16 = (2 * ks + b_kp) ^ (r & 7);
            ldsm_x4(bF[buf][g * 4 + 0], bF[buf][g * 4 + 1], bF[buf][g * 4 + 2], bF[buf][g * 4 + 3],
                    sB + (uint32_t)r * BK + (uint32_t)(c16 << 4));
        }
    };

    // wait for stage 0, preload its ks=0 fragments
    CP_WAIT2();
    __syncthreads();
    load_frags(0, sb, sb + STAGE_A_BYTES, 0);

    int buf = 0;
    for (int i = 0; i < KT; ++i) {
        // issue loads for stage i+3 (slot (i+3)%4 was freed by barrier at end of prev iter)
        int nk = i + STAGES - 1;
        if (nk < KT) {
            int s = nk % STAGES;
            uint32_t sA = sb + s * STAGE_BYTES;
            uint32_t sB = sA + STAGE_A_BYTES;
            size_t k0 = (size_t)nk * BK;
            #pragma unroll
            for (int t = 0; t < 4; t++)
                cp_async16(sA + ld_soff + t * 32 * BK, gA + ld_goff + (size_t)(t * 32) * KDIM + k0);
            #pragma unroll
            for (int t = 0; t < 8; t++)
                cp_async16(sB + ld_soff + t * 32 * BK, gB + ld_goff + (size_t)(t * 32) * KDIM + k0);
        }
        CP_COMMIT();

        const int s = i % STAGES;
        const uint32_t sA = sb + s * STAGE_BYTES;
        const uint32_t sB = sA + STAGE_A_BYTES;

        #pragma unroll
        for (int ks = 0; ks < 4; ks++) {
            // prefetch next fragments into the other buffer BEFORE this ks's MMAs
            if (ks < 3) {
                load_frags(buf ^ 1, sA, sB, ks + 1);
            } else if (i < KT - 1) {
                // advance to next stage: data guaranteed by wait_group 2, then
                // barrier so the cp.async issued next iter can't overwrite a
                // stage still being read (all its frags are now in registers).
                CP_WAIT2();
                __syncthreads();
                const int s2 = (i + 1) % STAGES;
                const uint32_t sA2 = sb + s2 * STAGE_BYTES;
                const uint32_t sB2 = sA2 + STAGE_A_BYTES;
                load_frags(buf ^ 1, sA2, sB2, 0);
            }
            #pragma unroll
            for (int mi = 0; mi < 4; mi++)
                #pragma unroll
                for (int ni = 0; ni < 8; ni++)
                    mma_fp8(acc[mi][ni][0], acc[mi][ni][1], acc[mi][ni][2], acc[mi][ni][3],
                            aF[buf][mi * 4], aF[buf][mi * 4 + 1], aF[buf][mi * 4 + 2], aF[buf][mi * 4 + 3],
                            bF[buf][ni * 2], bF[buf][ni * 2 + 1]);
            buf ^= 1;
        }
    }

    // ---- epilogue: dequant + store ----
    const float inv = g_scales[2];
    #pragma unroll
    for (int mi = 0; mi < 4; mi++) {
        int r = m0 + wm * 64 + mi * 16 + (lane >> 2);
        #pragma unroll
        for (int ni = 0; ni < 8; ni++) {
            int c = n0 + wn * 64 + ni * 8 + 2 * (lane & 3);
            float2 v0 = make_float2(acc[mi][ni][0] * inv, acc[mi][ni][1] * inv);
            float2 v1 = make_float2(acc[mi][ni][2] * inv, acc[mi][ni][3] * inv);
            *reinterpret_cast<float2*>(out + (size_t)r * NDIM + c) = v0;
            *reinterpret_cast<float2*>(out + (size_t)(r + 8) * NDIM + c) = v1;
        }
    }
}

// ---------------- host launch ----------------
extern "C" void kernel_launch(void* const* d_in, const int* in_sizes, int n_in,
                              void* d_out, int out_size) {
    const float* x = (const float*)d_in[0];
    const float* w = (const float*)d_in[1];
    if (n_in >= 2 && in_sizes[0] < in_sizes[1]) { const float* t = x; x = w; w = t; }
    float* out = (float*)d_out;

    zero_kernel<<<1, 32>>>();
    absmax_kernel<<<2048, 256>>>((const float4*)x, (MDIM * KDIM) / 4, 0);
    absmax_kernel<<<512, 256>>>((const float4*)w, (KDIM * NDIM) / 4, 1);
    scale_kernel<<<1, 1>>>();
    quant_x_kernel<<<(MDIM / 4) * (KDIM / 256), 256>>>((const float4*)x);
    {
        dim3 tb(32, 8), tg(NDIM / 32, KDIM / 32);
        quant_wt_kernel<<<tg, tb>>>(w);
    }

    cudaFuncSetAttribute(gemm_kernel, cudaFuncAttributeMaxDynamicSharedMemorySize, GEMM_SMEM);
    gemm_kernel<<<dim3(NDIM / BN, MDIM / BM), 256, GEMM_SMEM>>>(out);
}

// round 7
// speedup vs baseline: 1.1966x; 1.1966x over previous
#include <cuda_runtime.h>
#include <cuda_fp8.h>
#include <cstdint>
#include <cstddef>

// ---------------- problem dims ----------------
#define MDIM 16384
#define KDIM 4096
#define NDIM 4096

// ---------------- GEMM tiling ----------------
#define BM 128
#define BN 256
#define BK 128            // fp8 bytes per k-step
#define STAGES 4
#define KT (KDIM / BK)    // 32 k-iterations
#define STAGE_A_BYTES (BM * BK)                    // 16 KB
#define STAGE_B_BYTES (BN * BK)                    // 32 KB
#define STAGE_BYTES (STAGE_A_BYTES + STAGE_B_BYTES)  // 48 KB
#define GEMM_SMEM (STAGES * STAGE_BYTES)           // 192 KB

// ---------------- scratch (no allocations allowed) ----------------
__device__ __align__(1024) unsigned char g_xq[(size_t)MDIM * KDIM];   // 64 MB fp8 [M,K]
__device__ __align__(1024) unsigned char g_wqt[(size_t)NDIM * KDIM];  // 16 MB fp8 [N,K]
__device__ unsigned g_amax[2];
__device__ float g_scales[3];   // sx, sw, 1/(sx*sw)

// ---------------- helpers ----------------
__device__ __forceinline__ uint32_t smem_u32(const void* p) {
    uint32_t a;
    asm("{ .reg .u64 t; cvta.to.shared.u64 t, %1; cvt.u32.u64 %0, t; }" : "=r"(a) : "l"(p));
    return a;
}

__device__ __forceinline__ void cp_async16(uint32_t saddr, const void* gptr) {
    asm volatile("cp.async.cg.shared.global [%0], [%1], 16;" :: "r"(saddr), "l"(gptr) : "memory");
}

#define CP_COMMIT() asm volatile("cp.async.commit_group;" ::: "memory")
#define CP_WAIT2()  asm volatile("cp.async.wait_group 2;" ::: "memory")

__device__ __forceinline__ void ldsm_x4(uint32_t& r0, uint32_t& r1, uint32_t& r2, uint32_t& r3, uint32_t addr) {
    asm volatile("ldmatrix.sync.aligned.m8n8.x4.shared.b16 {%0,%1,%2,%3}, [%4];"
                 : "=r"(r0), "=r"(r1), "=r"(r2), "=r"(r3) : "r"(addr));
}

__device__ __forceinline__ void mma_fp8(float& c0, float& c1, float& c2, float& c3,
                                        uint32_t a0, uint32_t a1, uint32_t a2, uint32_t a3,
                                        uint32_t b0, uint32_t b1) {
    asm volatile(
        "mma.sync.aligned.m16n8k32.row.col.f32.e4m3.e4m3.f32 "
        "{%0,%1,%2,%3}, {%4,%5,%6,%7}, {%8,%9}, {%0,%1,%2,%3};"
        : "+f"(c0), "+f"(c1), "+f"(c2), "+f"(c3)
        : "r"(a0), "r"(a1), "r"(a2), "r"(a3), "r"(b0), "r"(b1));
}

// ---------------- pre-pass kernels ----------------
__global__ void zero_kernel() {
    if (threadIdx.x < 2) g_amax[threadIdx.x] = 0u;
}

__global__ void absmax_kernel(const float4* __restrict__ v, int n4, int slot) {
    float m = 0.f;
    for (int i = blockIdx.x * blockDim.x + threadIdx.x; i < n4; i += gridDim.x * blockDim.x) {
        float4 t = v[i];
        m = fmaxf(m, fmaxf(fmaxf(fabsf(t.x), fabsf(t.y)), fmaxf(fabsf(t.z), fabsf(t.w))));
    }
    #pragma unroll
    for (int o = 16; o; o >>= 1) m = fmaxf(m, __shfl_xor_sync(0xFFFFFFFFu, m, o));
    if ((threadIdx.x & 31) == 0) atomicMax(&g_amax[slot], __float_as_uint(m));
}

__global__ void scale_kernel() {
    float sx = 448.0f / __uint_as_float(g_amax[0]);
    float sw = 448.0f / __uint_as_float(g_amax[1]);
    g_scales[0] = sx;
    g_scales[1] = sw;
    g_scales[2] = 1.0f / (sx * sw);
}

// quantize x [M,K] fp32 -> fp8 e4m3 (same layout)
__global__ void quant_x_kernel(const float4* __restrict__ x) {
    float s = g_scales[0];
    unsigned i = blockIdx.x * blockDim.x + threadIdx.x;
    float4 v = x[i];
    unsigned lo = __nv_cvt_float2_to_fp8x2(make_float2(v.x * s, v.y * s), __NV_SATFINITE, __NV_E4M3);
    unsigned hi = __nv_cvt_float2_to_fp8x2(make_float2(v.z * s, v.w * s), __NV_SATFINITE, __NV_E4M3);
    reinterpret_cast<unsigned*>(g_xq)[i] = (lo & 0xFFFFu) | (hi << 16);
}

// quantize + transpose w [K,N] fp32 -> wq_t [N,K] fp8
__global__ void quant_wt_kernel(const float* __restrict__ w) {
    __shared__ unsigned char tile[32][33];
    float s = g_scales[1];
    int n0 = blockIdx.x * 32, k0 = blockIdx.y * 32;
    int tx = threadIdx.x, ty = threadIdx.y;   // 32 x 8
    #pragma unroll
    for (int j = 0; j < 4; j++) {
        int k = k0 + ty + j * 8;
        float v = w[(size_t)k * NDIM + n0 + tx] * s;
        tile[ty + j * 8][tx] = __nv_cvt_float_to_fp8(v, __NV_SATFINITE, __NV_E4M3);
    }
    __syncthreads();
    #pragma unroll
    for (int j = 0; j < 4; j++) {
        int r = ty + j * 8;
        g_wqt[(size_t)(n0 + r) * KDIM + k0 + tx] = tile[tx][r];
    }
}

// ---------------- fp8 GEMM via mma.sync m16n8k32 ----------------
// CTA: 128x256, 16 warps (2x8), warp tile 64x32. 4-stage cp.async pipeline.
// 512 threads -> 4 warps/SMSP for latency hiding; ~120 regs/thread, no spills.
__global__ void __launch_bounds__(512, 1) gemm_kernel(float* __restrict__ out) {
    extern __shared__ __align__(1024) unsigned char smem[];
    const uint32_t sb = smem_u32(smem);

    const int tid = threadIdx.x;
    const int w = tid >> 5, lane = tid & 31;
    const int wm = w & 1;            // m offset 0/64
    const int wn = w >> 1;           // 0..7 -> n offset wn*32

    // ---- CTA raster swizzle: groups of 16(m) x 16(n) CTAs ----
    int lin = blockIdx.y * gridDim.x + blockIdx.x;   // grid = (16, 128)
    int grp = lin >> 8;
    int rem = lin & 255;
    const int m0 = (grp * 16 + (rem & 15)) * BM;
    const int n0 = (rem >> 4) * BN;

    const unsigned char* gA = g_xq  + (size_t)m0 * KDIM;
    const unsigned char* gB = g_wqt + (size_t)n0 * KDIM;

    // ---- cp.async mapping: 512 threads, 16B chunks ----
    // rows 0..63 per thread; A needs 128 rows (2 chunks), B 256 rows (4 chunks)
    const int ld_row0 = tid >> 3;              // 0..63
    const int ld_c16  = tid & 7;               // 16B column
    const uint32_t ld_soff = (uint32_t)ld_row0 * BK + (uint32_t)((ld_c16 ^ (ld_row0 & 7)) << 4);
    const size_t   ld_goff = (size_t)ld_row0 * KDIM + (size_t)(ld_c16 << 4);

    // ---- ldmatrix per-lane addressing ----
    int a_row[4];
    #pragma unroll
    for (int mi = 0; mi < 4; mi++) a_row[mi] = wm * 64 + mi * 16 + (lane & 15);
    const int a_kh = lane >> 4;
    int b_row[2];
    #pragma unroll
    for (int g = 0; g < 2; g++) b_row[g] = wn * 32 + g * 16 + (lane & 7) + ((lane >> 4) << 3);
    const int b_kp = (lane >> 3) & 1;

    float acc[4][4][4];
    #pragma unroll
    for (int mi = 0; mi < 4; mi++)
        #pragma unroll
        for (int ni = 0; ni < 4; ni++)
            #pragma unroll
            for (int q = 0; q < 4; q++) acc[mi][ni][q] = 0.f;

    // ---- prologue: load stages 0..2 ----
    #pragma unroll
    for (int s = 0; s < STAGES - 1; s++) {
        uint32_t sA = sb + s * STAGE_BYTES;
        uint32_t sB = sA + STAGE_A_BYTES;
        size_t k0 = (size_t)s * BK;
        #pragma unroll
        for (int t = 0; t < 2; t++)
            cp_async16(sA + ld_soff + t * 64 * BK, gA + ld_goff + (size_t)(t * 64) * KDIM + k0);
        #pragma unroll
        for (int t = 0; t < 4; t++)
            cp_async16(sB + ld_soff + t * 64 * BK, gB + ld_goff + (size_t)(t * 64) * KDIM + k0);
        CP_COMMIT();
    }

    // ---- mainloop ----
    for (int i = 0; i < KT; ++i) {
        CP_WAIT2();
        __syncthreads();

        // issue loads for stage i+3 (overwrites stage computed at iter i-1)
        int nk = i + STAGES - 1;
        if (nk < KT) {
            int s = nk % STAGES;
            uint32_t sA = sb + s * STAGE_BYTES;
            uint32_t sB = sA + STAGE_A_BYTES;
            size_t k0 = (size_t)nk * BK;
            #pragma unroll
            for (int t = 0; t < 2; t++)
                cp_async16(sA + ld_soff + t * 64 * BK, gA + ld_goff + (size_t)(t * 64) * KDIM + k0);
            #pragma unroll
            for (int t = 0; t < 4; t++)
                cp_async16(sB + ld_soff + t * 64 * BK, gB + ld_goff + (size_t)(t * 64) * KDIM + k0);
        }
        CP_COMMIT();

        // compute stage i
        const int s = i % STAGES;
        const uint32_t sA = sb + s * STAGE_BYTES;
        const uint32_t sB = sA + STAGE_A_BYTES;

        #pragma unroll
        for (int ks = 0; ks < 4; ks++) {
            uint32_t aF[4][4];
            #pragma unroll
            for (int mi = 0; mi < 4; mi++) {
                int r = a_row[mi];
                int c16 = (2 * ks + a_kh) ^ (r & 7);
                ldsm_x4(aF[mi][0], aF[mi][1], aF[mi][2], aF[mi][3],
                        sA + (uint32_t)r * BK + (uint32_t)(c16 << 4));
            }
            uint32_t bF[8];
            #pragma unroll
            for (int g = 0; g < 2; g++) {
                int r = b_row[g];
                int c16 = (2 * ks + b_kp) ^ (r & 7);
                ldsm_x4(bF[g * 4 + 0], bF[g * 4 + 1], bF[g * 4 + 2], bF[g * 4 + 3],
                        sB + (uint32_t)r * BK + (uint32_t)(c16 << 4));
            }
            #pragma unroll
            for (int mi = 0; mi < 4; mi++)
                #pragma unroll
                for (int ni = 0; ni < 4; ni++)
                    mma_fp8(acc[mi][ni][0], acc[mi][ni][1], acc[mi][ni][2], acc[mi][ni][3],
                            aF[mi][0], aF[mi][1], aF[mi][2], aF[mi][3],
                            bF[ni * 2], bF[ni * 2 + 1]);
        }
    }

    // ---- epilogue: dequant + store ----
    const float inv = g_scales[2];
    #pragma unroll
    for (int mi = 0; mi < 4; mi++) {
        int r = m0 + wm * 64 + mi * 16 + (lane >> 2);
        #pragma unroll
        for (int ni = 0; ni < 4; ni++) {
            int c = n0 + wn * 32 + ni * 8 + 2 * (lane & 3);
            float2 v0 = make_float2(acc[mi][ni][0] * inv, acc[mi][ni][1] * inv);
            float2 v1 = make_float2(acc[mi][ni][2] * inv, acc[mi][ni][3] * inv);
            *reinterpret_cast<float2*>(out + (size_t)r * NDIM + c) = v0;
            *reinterpret_cast<float2*>(out + (size_t)(r + 8) * NDIM + c) = v1;
        }
    }
}

// ---------------- host launch ----------------
extern "C" void kernel_launch(void* const* d_in, const int* in_sizes, int n_in,
                              void* d_out, int out_size) {
    const float* x = (const float*)d_in[0];
    const float* w = (const float*)d_in[1];
    if (n_in >= 2 && in_sizes[0] < in_sizes[1]) { const float* t = x; x = w; w = t; }
    float* out = (float*)d_out;

    zero_kernel<<<1, 32>>>();
    absmax_kernel<<<2048, 256>>>((const float4*)x, (MDIM * KDIM) / 4, 0);
    absmax_kernel<<<512, 256>>>((const float4*)w, (KDIM * NDIM) / 4, 1);
    scale_kernel<<<1, 1>>>();
    quant_x_kernel<<<(MDIM / 4) * (KDIM / 256), 256>>>((const float4*)x);
    {
        dim3 tb(32, 8), tg(NDIM / 32, KDIM / 32);
        quant_wt_kernel<<<tg, tb>>>(w);
    }

    cudaFuncSetAttribute(gemm_kernel, cudaFuncAttributeMaxDynamicSharedMemorySize, GEMM_SMEM);
    gemm_kernel<<<dim3(NDIM / BN, MDIM / BM), 512, GEMM_SMEM>>>(out);
}

// round 8
// speedup vs baseline: 1.2233x; 1.0223x over previous
#include <cuda_runtime.h>
#include <cuda_fp8.h>
#include <cstdint>
#include <cstddef>

// ---------------- problem dims ----------------
#define MDIM 16384
#define KDIM 4096
#define NDIM 4096

// ---------------- GEMM tiling ----------------
#define BM 128
#define BN 256
#define BK 128            // fp8 bytes per k-step
#define STAGES 4
#define KT (KDIM / BK)    // 32 k-iterations
#define STAGE_A_BYTES (BM * BK)                    // 16 KB
#define STAGE_B_BYTES (BN * BK)                    // 32 KB
#define STAGE_BYTES (STAGE_A_BYTES + STAGE_B_BYTES)  // 48 KB
#define GEMM_SMEM (STAGES * STAGE_BYTES)           // 192 KB

// ---------------- scratch (no allocations allowed) ----------------
__device__ __align__(1024) unsigned char g_xq[(size_t)MDIM * KDIM];   // 64 MB fp8 [M,K]
__device__ __align__(1024) unsigned char g_wqt[(size_t)NDIM * KDIM];  // 16 MB fp8 [N,K]
__device__ unsigned g_amax[2];   // zero at module load; atomicMax idempotent across replays

// ---------------- helpers ----------------
__device__ __forceinline__ uint32_t smem_u32(const void* p) {
    uint32_t a;
    asm("{ .reg .u64 t; cvta.to.shared.u64 t, %1; cvt.u32.u64 %0, t; }" : "=r"(a) : "l"(p));
    return a;
}

__device__ __forceinline__ void cp_async16(uint32_t saddr, const void* gptr) {
    asm volatile("cp.async.cg.shared.global [%0], [%1], 16;" :: "r"(saddr), "l"(gptr) : "memory");
}

#define CP_COMMIT() asm volatile("cp.async.commit_group;" ::: "memory")
#define CP_WAIT2()  asm volatile("cp.async.wait_group 2;" ::: "memory")

__device__ __forceinline__ void ldsm_x4(uint32_t& r0, uint32_t& r1, uint32_t& r2, uint32_t& r3, uint32_t addr) {
    asm volatile("ldmatrix.sync.aligned.m8n8.x4.shared.b16 {%0,%1,%2,%3}, [%4];"
                 : "=r"(r0), "=r"(r1), "=r"(r2), "=r"(r3) : "r"(addr));
}

__device__ __forceinline__ void mma_fp8(float& c0, float& c1, float& c2, float& c3,
                                        uint32_t a0, uint32_t a1, uint32_t a2, uint32_t a3,
                                        uint32_t b0, uint32_t b1) {
    asm volatile(
        "mma.sync.aligned.m16n8k32.row.col.f32.e4m3.e4m3.f32 "
        "{%0,%1,%2,%3}, {%4,%5,%6,%7}, {%8,%9}, {%0,%1,%2,%3};"
        : "+f"(c0), "+f"(c1), "+f"(c2), "+f"(c3)
        : "r"(a0), "r"(a1), "r"(a2), "r"(a3), "r"(b0), "r"(b1));
}

// ---------------- fused absmax (x blocks 0..2047, w blocks 2048..2559) ----------------
__global__ void absmax_kernel(const float4* __restrict__ x, const float4* __restrict__ w) {
    __shared__ float red[8];
    const int b = blockIdx.x;
    const float4* v;
    int n4, slot, bid, nb;
    if (b < 2048) { v = x; n4 = (MDIM / 4) * KDIM; slot = 0; bid = b;        nb = 2048; }
    else          { v = w; n4 = (KDIM / 4) * NDIM; slot = 1; bid = b - 2048; nb = 512;  }

    float m = 0.f;
    for (int i = bid * 256 + threadIdx.x; i < n4; i += nb * 256) {
        float4 t = v[i];
        m = fmaxf(m, fmaxf(fmaxf(fabsf(t.x), fabsf(t.y)), fmaxf(fabsf(t.z), fabsf(t.w))));
    }
    #pragma unroll
    for (int o = 16; o; o >>= 1) m = fmaxf(m, __shfl_xor_sync(0xFFFFFFFFu, m, o));
    const int wid = threadIdx.x >> 5, lane = threadIdx.x & 31;
    if (lane == 0) red[wid] = m;
    __syncthreads();
    if (wid == 0) {
        m = (lane < 8) ? red[lane] : 0.f;
        #pragma unroll
        for (int o = 4; o; o >>= 1) m = fmaxf(m, __shfl_xor_sync(0xFFFFFFFFu, m, o));
        if (lane == 0) atomicMax(&g_amax[slot], __float_as_uint(m));
    }
}

// quantize x [M,K] fp32 -> fp8 e4m3 (same layout); 4 float4 per thread
__global__ void quant_x_kernel(const float4* __restrict__ x) {
    const float s = 448.0f / __uint_as_float(g_amax[0]);
    unsigned i0 = blockIdx.x * 1024 + threadIdx.x;
    #pragma unroll
    for (int j = 0; j < 4; j++) {
        unsigned i = i0 + j * 256;
        float4 v = x[i];
        unsigned lo = __nv_cvt_float2_to_fp8x2(make_float2(v.x * s, v.y * s), __NV_SATFINITE, __NV_E4M3);
        unsigned hi = __nv_cvt_float2_to_fp8x2(make_float2(v.z * s, v.w * s), __NV_SATFINITE, __NV_E4M3);
        reinterpret_cast<unsigned*>(g_xq)[i] = (lo & 0xFFFFu) | (hi << 16);
    }
}

// quantize + transpose w [K,N] fp32 -> wq_t [N,K] fp8; 64x64 tile, vectorized I/O
__global__ void quant_wt_kernel(const float* __restrict__ w) {
    __shared__ unsigned tile[64][17];   // packed 4 n-bytes per word, padded
    const float s = 448.0f / __uint_as_float(g_amax[1]);
    const int n0 = blockIdx.x * 64, k0 = blockIdx.y * 64;
    const int t = threadIdx.x;

    // phase 1: quantize 64(k) x 64(n), float4 loads, packed-uint smem writes
    {
        const int r = t >> 4;      // 0..15 (k row base)
        const int c = t & 15;      // float4 column (4 n's)
        #pragma unroll
        for (int j = 0; j < 4; j++) {
            int kl = r + j * 16;
            float4 v = *reinterpret_cast<const float4*>(
                w + (size_t)(k0 + kl) * NDIM + n0 + c * 4);
            unsigned lo = __nv_cvt_float2_to_fp8x2(make_float2(v.x * s, v.y * s), __NV_SATFINITE, __NV_E4M3);
            unsigned hi = __nv_cvt_float2_to_fp8x2(make_float2(v.z * s, v.w * s), __NV_SATFINITE, __NV_E4M3);
            tile[kl][c] = (lo & 0xFFFFu) | (hi << 16);
        }
    }
    __syncthreads();

    // phase 2: transpose out of smem, 16B store per thread
    {
        const int nl = t >> 2;            // 0..63 (n row)
        const int kc = t & 3;             // 16-byte k chunk
        const unsigned sh = (nl & 3) * 8;
        const int col = nl >> 2;
        unsigned o[4];
        #pragma unroll
        for (int q = 0; q < 4; q++) {
            unsigned b0 = (tile[kc * 16 + q * 4 + 0][col] >> sh) & 0xFFu;
            unsigned b1 = (tile[kc * 16 + q * 4 + 1][col] >> sh) & 0xFFu;
            unsigned b2 = (tile[kc * 16 + q * 4 + 2][col] >> sh) & 0xFFu;
            unsigned b3 = (tile[kc * 16 + q * 4 + 3][col] >> sh) & 0xFFu;
            o[q] = b0 | (b1 << 8) | (b2 << 16) | (b3 << 24);
        }
        *reinterpret_cast<uint4*>(g_wqt + (size_t)(n0 + nl) * KDIM + k0 + kc * 16) =
            make_uint4(o[0], o[1], o[2], o[3]);
    }
}

// ---------------- fp8 GEMM via mma.sync m16n8k32 ----------------
// CTA: 128x256, 16 warps (2x8), warp tile 64x32. 4-stage cp.async pipeline.
__global__ void __launch_bounds__(512, 1) gemm_kernel(float* __restrict__ out) {
    extern __shared__ __align__(1024) unsigned char smem[];
    const uint32_t sb = smem_u32(smem);

    const int tid = threadIdx.x;
    const int w = tid >> 5, lane = tid & 31;
    const int wm = w & 1;            // m offset 0/64
    const int wn = w >> 1;           // 0..7 -> n offset wn*32

    // ---- CTA raster swizzle: groups of 16(m) x 16(n) CTAs ----
    int lin = blockIdx.y * gridDim.x + blockIdx.x;   // grid = (16, 128)
    int grp = lin >> 8;
    int rem = lin & 255;
    const int m0 = (grp * 16 + (rem & 15)) * BM;
    const int n0 = (rem >> 4) * BN;

    const unsigned char* gA = g_xq  + (size_t)m0 * KDIM;
    const unsigned char* gB = g_wqt + (size_t)n0 * KDIM;

    // ---- cp.async mapping: 512 threads, 16B chunks ----
    const int ld_row0 = tid >> 3;              // 0..63
    const int ld_c16  = tid & 7;               // 16B column
    const uint32_t ld_soff = (uint32_t)ld_row0 * BK + (uint32_t)((ld_c16 ^ (ld_row0 & 7)) << 4);
    const size_t   ld_goff = (size_t)ld_row0 * KDIM + (size_t)(ld_c16 << 4);

    // ---- ldmatrix per-lane addressing ----
    int a_row[4];
    #pragma unroll
    for (int mi = 0; mi < 4; mi++) a_row[mi] = wm * 64 + mi * 16 + (lane & 15);
    const int a_kh = lane >> 4;
    int b_row[2];
    #pragma unroll
    for (int g = 0; g < 2; g++) b_row[g] = wn * 32 + g * 16 + (lane & 7) + ((lane >> 4) << 3);
    const int b_kp = (lane >> 3) & 1;

    float acc[4][4][4];
    #pragma unroll
    for (int mi = 0; mi < 4; mi++)
        #pragma unroll
        for (int ni = 0; ni < 4; ni++)
            #pragma unroll
            for (int q = 0; q < 4; q++) acc[mi][ni][q] = 0.f;

    // ---- prologue: load stages 0..2 ----
    #pragma unroll
    for (int s = 0; s < STAGES - 1; s++) {
        uint32_t sA = sb + s * STAGE_BYTES;
        uint32_t sB = sA + STAGE_A_BYTES;
        size_t k0 = (size_t)s * BK;
        #pragma unroll
        for (int t = 0; t < 2; t++)
            cp_async16(sA + ld_soff + t * 64 * BK, gA + ld_goff + (size_t)(t * 64) * KDIM + k0);
        #pragma unroll
        for (int t = 0; t < 4; t++)
            cp_async16(sB + ld_soff + t * 64 * BK, gB + ld_goff + (size_t)(t * 64) * KDIM + k0);
        CP_COMMIT();
    }

    // ---- mainloop ----
    for (int i = 0; i < KT; ++i) {
        CP_WAIT2();
        __syncthreads();

        int nk = i + STAGES - 1;
        if (nk < KT) {
            int s = nk % STAGES;
            uint32_t sA = sb + s * STAGE_BYTES;
            uint32_t sB = sA + STAGE_A_BYTES;
            size_t k0 = (size_t)nk * BK;
            #pragma unroll
            for (int t = 0; t < 2; t++)
                cp_async16(sA + ld_soff + t * 64 * BK, gA + ld_goff + (size_t)(t * 64) * KDIM + k0);
            #pragma unroll
            for (int t = 0; t < 4; t++)
                cp_async16(sB + ld_soff + t * 64 * BK, gB + ld_goff + (size_t)(t * 64) * KDIM + k0);
        }
        CP_COMMIT();

        const int s = i % STAGES;
        const uint32_t sA = sb + s * STAGE_BYTES;
        const uint32_t sB = sA + STAGE_A_BYTES;

        #pragma unroll
        for (int ks = 0; ks < 4; ks++) {
            uint32_t aF[4][4];
            #pragma unroll
            for (int mi = 0; mi < 4; mi++) {
                int r = a_row[mi];
                int c16 = (2 * ks + a_kh) ^ (r & 7);
                ldsm_x4(aF[mi][0], aF[mi][1], aF[mi][2], aF[mi][3],
                        sA + (uint32_t)r * BK + (uint32_t)(c16 << 4));
            }
            uint32_t bF[8];
            #pragma unroll
            for (int g = 0; g < 2; g++) {
                int r = b_row[g];
                int c16 = (2 * ks + b_kp) ^ (r & 7);
                ldsm_x4(bF[g * 4 + 0], bF[g * 4 + 1], bF[g * 4 + 2], bF[g * 4 + 3],
                        sB + (uint32_t)r * BK + (uint32_t)(c16 << 4));
            }
            #pragma unroll
            for (int mi = 0; mi < 4; mi++)
                #pragma unroll
                for (int ni = 0; ni < 4; ni++)
                    mma_fp8(acc[mi][ni][0], acc[mi][ni][1], acc[mi][ni][2], acc[mi][ni][3],
                            aF[mi][0], aF[mi][1], aF[mi][2], aF[mi][3],
                            bF[ni * 2], bF[ni * 2 + 1]);
        }
    }

    // ---- epilogue: dequant + store ----
    const float ax = __uint_as_float(g_amax[0]);
    const float aw = __uint_as_float(g_amax[1]);
    const float inv = ax * aw * (1.0f / (448.0f * 448.0f));
    #pragma unroll
    for (int mi = 0; mi < 4; mi++) {
        int r = m0 + wm * 64 + mi * 16 + (lane >> 2);
        #pragma unroll
        for (int ni = 0; ni < 4; ni++) {
            int c = n0 + wn * 32 + ni * 8 + 2 * (lane & 3);
            float2 v0 = make_float2(acc[mi][ni][0] * inv, acc[mi][ni][1] * inv);
            float2 v1 = make_float2(acc[mi][ni][2] * inv, acc[mi][ni][3] * inv);
            *reinterpret_cast<float2*>(out + (size_t)r * NDIM + c) = v0;
            *reinterpret_cast<float2*>(out + (size_t)(r + 8) * NDIM + c) = v1;
        }
    }
}

// ---------------- host launch ----------------
extern "C" void kernel_launch(void* const* d_in, const int* in_sizes, int n_in,
                              void* d_out, int out_size) {
    const float* x = (const float*)d_in[0];
    const float* w = (const float*)d_in[1];
    if (n_in >= 2 && in_sizes[0] < in_sizes[1]) { const float* t = x; x = w; w = t; }
    float* out = (float*)d_out;

    absmax_kernel<<<2560, 256>>>((const float4*)x, (const float4*)w);
    quant_x_kernel<<<(MDIM / 4) * (KDIM / 1024), 256>>>((const float4*)x);
    {
        dim3 tg(NDIM / 64, KDIM / 64);
        quant_wt_kernel<<<tg, 256>>>(w);
    }

    cudaFuncSetAttribute(gemm_kernel, cudaFuncAttributeMaxDynamicSharedMemorySize, GEMM_SMEM);
    gemm_kernel<<<dim3(NDIM / BN, MDIM / BM), 512, GEMM_SMEM>>>(out);
}